// round 12
// baseline (speedup 1.0000x reference)
#include <cuda_runtime.h>
#include <stdint.h>

// =====================================================================
// PatchNCELoss: loss[r] = lse_c( inv_t * q[r]·k[c] ) - inv_t * q[r]·k[r]
// R11: int8 IMMA limb GEMM.  q' = q*inv_t*log2e quantized to 16-bit
// fixed (2 s8 limbs, scales 1 and 2^-8); k quantized (scales 2^-4,
// 2^-12).  logit_log2 = 2^-4*S_hh + 2^-12*(S_hl+S_lh).  m16n8k32.s8
// mma = 2x MACs/instr of bf16 k16 -> tensor-issue floor halves.
// Persistent 148-CTA scheduling, pairwise sync, per-tile partials.
// =====================================================================

#define N_TOT 8192
#define DDIM  256
#define INV_T_F     14.285714285714286f
#define QSCALE_F    20.609929155556627f   /* inv_t * log2(e) */
#define LN2_F       0.6931471805599453f

#define NCTA      148
#define ROWTILES  64
#define COLTILES  64                       // 128-col tiles
#define UNITS     (ROWTILES * COLTILES)    // 4096
#define CHUNKS_PT 2                        // b_hi, b_lo
#define NSLOT     256                      // 64 coltiles x 4 warp_n

// ---- device scratch ----
__device__ __align__(256) char g_Ah[N_TOT * DDIM];
__device__ __align__(256) char g_Al[N_TOT * DDIM];
__device__ __align__(256) char g_Bh[N_TOT * DDIM];
__device__ __align__(256) char g_Bl[N_TOT * DDIM];
__device__ float g_diag[N_TOT];
__device__ float g_m[N_TOT * NSLOT];
__device__ float g_s[N_TOT * NSLOT];

// ---------------- PTX helpers ----------------
__device__ __forceinline__ uint32_t smem_u32(const void* p) {
    uint32_t a;
    asm("{ .reg .u64 t; cvta.to.shared.u64 t, %1; cvt.u32.u64 %0, t; }"
        : "=r"(a) : "l"(p));
    return a;
}
__device__ __forceinline__ void cp16(uint32_t dst, const void* src) {
    asm volatile("cp.async.cg.shared.global [%0], [%1], 16;"
                 :: "r"(dst), "l"(src) : "memory");
}
__device__ __forceinline__ void cp_commit() {
    asm volatile("cp.async.commit_group;" ::: "memory");
}
template <int N>
__device__ __forceinline__ void cp_wait() {
    asm volatile("cp.async.wait_group %0;" :: "n"(N) : "memory");
}
__device__ __forceinline__ void pair_bar(int id) {
    asm volatile("bar.sync %0, 64;" :: "r"(id) : "memory");
}
__device__ __forceinline__ void ldsm4(uint32_t* r, uint32_t addr) {
    asm volatile("ldmatrix.sync.aligned.m8n8.x4.shared.b16 {%0,%1,%2,%3}, [%4];"
                 : "=r"(r[0]), "=r"(r[1]), "=r"(r[2]), "=r"(r[3]) : "r"(addr));
}
// s8 mma m16n8k32: d(s32) += A(s8) x B(s8)
__device__ __forceinline__ void mma_s8(int* d, const uint32_t* a, const uint32_t* b) {
    asm volatile(
        "mma.sync.aligned.m16n8k32.row.col.s32.s8.s8.s32 "
        "{%0,%1,%2,%3}, {%4,%5,%6,%7}, {%8,%9}, {%0,%1,%2,%3};"
        : "+r"(d[0]), "+r"(d[1]), "+r"(d[2]), "+r"(d[3])
        : "r"(a[0]), "r"(a[1]), "r"(a[2]), "r"(a[3]), "r"(b[0]), "r"(b[1]));
}
__device__ __forceinline__ float ex2f(float x) {
    float y;
    asm("ex2.approx.ftz.f32 %0, %1;" : "=f"(y) : "f"(x));
    return y;
}

// ---------------------------------------------------------------------
// Kernel 1: prep — int8 limb quantization + exact fp32 diagonal dot.
// 256 threads / block, 4 rows per block, 4 elems / thread.
// ---------------------------------------------------------------------
__global__ void __launch_bounds__(256)
prep_kernel(const float* __restrict__ Q, const float* __restrict__ K) {
    const int row = blockIdx.x * 4 + (threadIdx.x >> 6);
    const int lt = threadIdx.x & 63;

    float4 q4 = ((const float4*)(Q + (size_t)row * DDIM))[lt];
    float4 k4 = ((const float4*)(K + (size_t)row * DDIM))[lt];

    float dot = q4.x * k4.x + q4.y * k4.y + q4.z * k4.z + q4.w * k4.w;

    float qv[4] = {q4.x, q4.y, q4.z, q4.w};
    float kv[4] = {k4.x, k4.y, k4.z, k4.w};
    char ah[4], al[4], bh[4], bl[4];
#pragma unroll
    for (int i = 0; i < 4; i++) {
        int Aq = __float2int_rn(qv[i] * (QSCALE_F * 256.0f));
        Aq = max(-32639, min(32639, Aq));
        int hi = (Aq + 128) >> 8;
        ah[i] = (char)hi;
        al[i] = (char)(Aq - (hi << 8));
        int Bq = __float2int_rn(kv[i] * 4096.0f);
        Bq = max(-32639, min(32639, Bq));
        int bhi = (Bq + 128) >> 8;
        bh[i] = (char)bhi;
        bl[i] = (char)(Bq - (bhi << 8));
    }
    size_t off = (size_t)row * DDIM + lt * 4;
    *(char4*)(g_Ah + off) = make_char4(ah[0], ah[1], ah[2], ah[3]);
    *(char4*)(g_Al + off) = make_char4(al[0], al[1], al[2], al[3]);
    *(char4*)(g_Bh + off) = make_char4(bh[0], bh[1], bh[2], bh[3]);
    *(char4*)(g_Bl + off) = make_char4(bl[0], bl[1], bl[2], bl[3]);

#pragma unroll
    for (int o = 16; o > 0; o >>= 1)
        dot += __shfl_xor_sync(0xffffffffu, dot, o);
    __shared__ float red[8];
    const int wid = threadIdx.x >> 5;
    if ((threadIdx.x & 31) == 0) red[wid] = dot;
    __syncthreads();
    if ((threadIdx.x & 63) == 0)
        g_diag[row] = red[wid] + red[wid + 1];
}

// ---------------------------------------------------------------------
// Kernel 2: persistent IMMA s8 GEMM + per-tile softmax partials.
// grid = 148. 256 threads = 8 warps, grid 2(M)x4(N), warp tile 64x32.
// Unit = 128 rows x 128 cols.  Per unit: chunk0 = B_hi (hh + lh passes),
// chunk1 = B_lo (hl pass).  Pairwise sync (warp pair owns 32 B-cols).
// SMEM: A = Ah|Al [128x256B] (64KB), B 3-stage ring (3x32KB).
// ---------------------------------------------------------------------
#define NSTAGE    3
#define A_BYTES   (2 * 128 * 256)          // 65536
#define B_STAGE   (128 * 256)              // 32768
#define SMEM_DYN  (512 + A_BYTES + NSTAGE * B_STAGE)

__global__ void __launch_bounds__(256, 1)
gemm_lse_kernel() {
    extern __shared__ char dsm[];
    const uint32_t base = (smem_u32(dsm) + 127u) & ~127u;
    const uint32_t A0 = base;                    // Ah [128][256B], then Al
    const uint32_t B0 = base + A_BYTES;

    const int tid = threadIdx.x;
    const int wid = tid >> 5, lane = tid & 31;
    const int warp_m = wid & 1;                  // 0..1 (rows of 64)
    const int warp_n = wid >> 1;                 // 0..3 (cols of 32)
    const int pair = warp_n;
    const int tp = tid & 63;

    const int ustart = (blockIdx.x * UNITS) / NCTA;
    const int uendall = ((blockIdx.x + 1) * UNITS) / NCTA;

    // ---- per-thread B load descriptors: pair's 32-col slice, 8x16B ----
    uint32_t bsrcoff[8], bdst[8];
#pragma unroll
    for (int ii = 0; ii < 8; ii++) {
        int idx = ii * 64 + tp;                 // 0..511
        int nB = pair * 32 + (idx >> 4);
        int kc = idx & 15;
        bsrcoff[ii] = (uint32_t)(nB * DDIM + kc * 16);
        bdst[ii] = (uint32_t)(nB * 256 + ((kc ^ (nB & 7)) << 4));
    }

    // ---- compute-side address precompute ----
    int rowA[4], rswA[4];
#pragma unroll
    for (int mi = 0; mi < 4; mi++) {
        rowA[mi] = warp_m * 64 + mi * 16 + (lane & 7) + ((lane & 8) ? 8 : 0);
        rswA[mi] = rowA[mi] & 7;
    }
    const int khalf = (lane >> 4) & 1;
    const int hhB = (lane >> 3) & 1;
    uint32_t bOff[2]; int bsw[2];
#pragma unroll
    for (int gp = 0; gp < 2; gp++) {
        int gg = 2 * gp + ((lane >> 4) & 1);
        int nB = warp_n * 32 + gg * 8 + (lane & 7);
        bOff[gp] = (uint32_t)(nB * 256);
        bsw[gp] = nB & 7;
    }

    int acc_hh[4][4][4], acc_cr[4][4][4];
#pragma unroll
    for (int mi = 0; mi < 4; mi++)
#pragma unroll
        for (int g = 0; g < 4; g++)
#pragma unroll
            for (int v = 0; v < 4; v++) { acc_hh[mi][g][v] = 0; acc_cr[mi][g][v] = 0; }

    for (int u0 = ustart; u0 < uendall; ) {
        const int rt = u0 >> 6;                  // rowtile (64 units each)
        const int u1 = min(uendall, (rt + 1) << 6);
        const int rowBase = rt << 7;
        const int nch = (u1 - u0) * CHUNKS_PT;

        // ---- load A (Ah,Al rows rowBase..+127), swizzled 16B chunks ----
        for (int ii = 0; ii < 16; ii++) {
            int idx = ii * 256 + tid;           // 0..4095
            int limb = idx >> 11;
            int rest = idx & 2047;
            int row = rest >> 4, kc = rest & 15;
            const char* src =
                (limb ? g_Al : g_Ah) + (size_t)(rowBase + row) * DDIM + kc * 16;
            cp16(A0 + limb * 32768 + row * 256 +
                 (((uint32_t)(kc ^ (row & 7))) << 4), src);
        }
        cp_commit();   // group: A

        auto loadB = [&](int gc) {
            int unit = u0 + (gc >> 1);
            int sub = gc & 1;                   // 0: B_hi, 1: B_lo
            int ctile = unit & 63;
            const char* bsrc = sub ? g_Bl : g_Bh;
            const char* srow = bsrc + (size_t)(ctile * 128) * DDIM;
            uint32_t dstB = B0 + (uint32_t)(gc % NSTAGE) * B_STAGE;
#pragma unroll
            for (int ii = 0; ii < 8; ii++)
                cp16(dstB + bdst[ii], srow + bsrcoff[ii]);
        };

        loadB(0); cp_commit();
        loadB(1); cp_commit();
        cp_wait<0>();
        __syncthreads();     // A + B0,B1 resident

        for (int c = 0; c < nch; c++) {
            cp_wait<1>();
            pair_bar(pair + 1);

            if (c + 2 < nch) loadB(c + 2);
            cp_commit();

            const int sub = c & 1;
            const uint32_t Bst = B0 + (uint32_t)(c % NSTAGE) * B_STAGE;

#pragma unroll
            for (int ks = 0; ks < 8; ks++) {
                const uint32_t ach = (uint32_t)(2 * ks + khalf);
                const uint32_t bch = (uint32_t)(2 * ks + hhB);
                uint32_t b[4][2];
#pragma unroll
                for (int gp = 0; gp < 2; gp++) {
                    uint32_t t4[4];
                    ldsm4(t4, Bst + bOff[gp] + ((bch ^ (uint32_t)bsw[gp]) << 4));
                    b[2 * gp][0] = t4[0]; b[2 * gp][1] = t4[1];
                    b[2 * gp + 1][0] = t4[2]; b[2 * gp + 1][1] = t4[3];
                }
                // pass 1: A_hi x B  ->  hh (sub0) or cross (sub1)
                {
                    uint32_t a[4][4];
#pragma unroll
                    for (int mi = 0; mi < 4; mi++)
                        ldsm4(a[mi], A0 + (uint32_t)rowA[mi] * 256 +
                                      (((ach ^ (uint32_t)rswA[mi])) << 4));
                    if (sub == 0) {
#pragma unroll
                        for (int mi = 0; mi < 4; mi++)
#pragma unroll
                            for (int g = 0; g < 4; g++)
                                mma_s8(acc_hh[mi][g], a[mi], b[g]);
                    } else {
#pragma unroll
                        for (int mi = 0; mi < 4; mi++)
#pragma unroll
                            for (int g = 0; g < 4; g++)
                                mma_s8(acc_cr[mi][g], a[mi], b[g]);
                    }
                }
                // pass 2 (B_hi chunks only): A_lo x B_hi -> cross
                if (sub == 0) {
                    uint32_t a[4][4];
#pragma unroll
                    for (int mi = 0; mi < 4; mi++)
                        ldsm4(a[mi], A0 + 32768u + (uint32_t)rowA[mi] * 256 +
                                      (((ach ^ (uint32_t)rswA[mi])) << 4));
#pragma unroll
                    for (int mi = 0; mi < 4; mi++)
#pragma unroll
                        for (int g = 0; g < 4; g++)
                            mma_s8(acc_cr[mi][g], a[mi], b[g]);
                }
            }

            if (sub == 1) {
                // ---- per-tile softmax partial in log2 domain ----
                const int unit = u0 + (c >> 1);
                const int slot = (unit & 63) * 4 + warp_n;
#pragma unroll
                for (int mi = 0; mi < 4; mi++) {
#pragma unroll
                    for (int p = 0; p < 2; p++) {
                        float t[8];
#pragma unroll
                        for (int g = 0; g < 4; g++) {
                            t[2 * g] = __int2float_rn(acc_hh[mi][g][2 * p]) * 0.0625f +
                                       __int2float_rn(acc_cr[mi][g][2 * p]) * 2.44140625e-4f;
                            t[2 * g + 1] = __int2float_rn(acc_hh[mi][g][2 * p + 1]) * 0.0625f +
                                           __int2float_rn(acc_cr[mi][g][2 * p + 1]) * 2.44140625e-4f;
                        }
                        float rm = t[0];
#pragma unroll
                        for (int i = 1; i < 8; i++) rm = fmaxf(rm, t[i]);
                        rm = fmaxf(rm, __shfl_xor_sync(0xffffffffu, rm, 1));
                        rm = fmaxf(rm, __shfl_xor_sync(0xffffffffu, rm, 2));
                        float ssum = 0.f;
#pragma unroll
                        for (int i = 0; i < 8; i++) ssum += ex2f(t[i] - rm);
                        ssum += __shfl_xor_sync(0xffffffffu, ssum, 1);
                        ssum += __shfl_xor_sync(0xffffffffu, ssum, 2);
                        if ((lane & 3) == 0) {
                            int row = rowBase + warp_m * 64 + mi * 16 +
                                      (lane >> 2) + 8 * p;
                            g_m[(size_t)row * NSLOT + slot] = rm;
                            g_s[(size_t)row * NSLOT + slot] = ssum;
                        }
                    }
                }
#pragma unroll
                for (int mi = 0; mi < 4; mi++)
#pragma unroll
                    for (int g = 0; g < 4; g++)
#pragma unroll
                        for (int v = 0; v < 4; v++) {
                            acc_hh[mi][g][v] = 0; acc_cr[mi][g][v] = 0;
                        }
            }
        }

        cp_wait<0>();
        __syncthreads();     // all pairs done before A overwrite
        u0 = u1;
    }
}

// ---------------------------------------------------------------------
// Kernel 3: combine 256 partials per row into the loss. 1 warp / row.
// ---------------------------------------------------------------------
__global__ void __launch_bounds__(256)
combine_kernel(float* __restrict__ out) {
    int row = (blockIdx.x * blockDim.x + threadIdx.x) >> 5;
    int lane = threadIdx.x & 31;
    if (row >= N_TOT) return;

    float4 mv0 = ((const float4*)(g_m + (size_t)row * NSLOT))[lane];
    float4 mv1 = ((const float4*)(g_m + (size_t)row * NSLOT))[lane + 32];
    float4 sv0 = ((const float4*)(g_s + (size_t)row * NSLOT))[lane];
    float4 sv1 = ((const float4*)(g_s + (size_t)row * NSLOT))[lane + 32];

    float M = fmaxf(fmaxf(fmaxf(mv0.x, mv0.y), fmaxf(mv0.z, mv0.w)),
                    fmaxf(fmaxf(mv1.x, mv1.y), fmaxf(mv1.z, mv1.w)));
#pragma unroll
    for (int o = 16; o > 0; o >>= 1)
        M = fmaxf(M, __shfl_xor_sync(0xffffffffu, M, o));

    float S = sv0.x * ex2f(mv0.x - M) + sv0.y * ex2f(mv0.y - M) +
              sv0.z * ex2f(mv0.z - M) + sv0.w * ex2f(mv0.w - M) +
              sv1.x * ex2f(mv1.x - M) + sv1.y * ex2f(mv1.y - M) +
              sv1.z * ex2f(mv1.z - M) + sv1.w * ex2f(mv1.w - M);
#pragma unroll
    for (int o = 16; o > 0; o >>= 1)
        S += __shfl_xor_sync(0xffffffffu, S, o);

    if (lane == 0)
        out[row] = LN2_F * (M + log2f(S)) - INV_T_F * g_diag[row];
}

// ---------------------------------------------------------------------
extern "C" void kernel_launch(void* const* d_in, const int* in_sizes, int n_in,
                              void* d_out, int out_size) {
    const float* Q = (const float*)d_in[0];
    const float* K = (const float*)d_in[1];
    float* out = (float*)d_out;

    cudaFuncSetAttribute(gemm_lse_kernel,
                         cudaFuncAttributeMaxDynamicSharedMemorySize, SMEM_DYN);

    prep_kernel<<<N_TOT / 4, 256>>>(Q, K);
    gemm_lse_kernel<<<NCTA, 256, SMEM_DYN>>>();
    combine_kernel<<<N_TOT * 32 / 256, 256>>>(out);
}

// round 13
// speedup vs baseline: 3.2725x; 3.2725x over previous
#include <cuda_runtime.h>
#include <cuda_bf16.h>
#include <stdint.h>

// =====================================================================
// PatchNCELoss: loss[r] = lse_c( inv_t * q[r]·k[c] ) - inv_t * q[r]·k[r]
// Q,K: [8192, 256] fp32.  bf16 hi/lo split -> 3 GEMM products fused into
// one mma.sync mainloop + per-tile log2-domain softmax partials.
// R13: revert to R10 bf16 core (s8 IMMA is slow on sm_103a fallback).
// + pair stagger (seed drift so epilogues de-align and HMMA pipe stays
// fed during MUFU bursts), dynamic SM count, A-frag preissue.
// =====================================================================

#define N_TOT 8192
#define DDIM  256
#define INV_T_F     14.285714285714286f
#define QSCALE_F    20.609929155556627f   /* inv_t * log2(e) */
#define LN2_F       0.6931471805599453f

#define COLTILES  32                       // 256-col tiles
#define UNITS     (64 * COLTILES)          // 2048
#define CHUNKS_PT 8                        // 4 k64 x {Kh, Kl}
#define NSLOT     128                      // 32 coltiles x 4 warp_n

// ---- device scratch ----
__device__ __align__(256) __nv_bfloat16 g_Qh[N_TOT * DDIM];
__device__ __align__(256) __nv_bfloat16 g_Ql[N_TOT * DDIM];
__device__ __align__(256) __nv_bfloat16 g_Kh[N_TOT * DDIM];
__device__ __align__(256) __nv_bfloat16 g_Kl[N_TOT * DDIM];
__device__ float g_diag[N_TOT];
__device__ float g_m[N_TOT * NSLOT];
__device__ float g_s[N_TOT * NSLOT];

// ---------------- PTX helpers ----------------
__device__ __forceinline__ uint32_t smem_u32(const void* p) {
    uint32_t a;
    asm("{ .reg .u64 t; cvta.to.shared.u64 t, %1; cvt.u32.u64 %0, t; }"
        : "=r"(a) : "l"(p));
    return a;
}
__device__ __forceinline__ void cp16(uint32_t dst, const void* src) {
    asm volatile("cp.async.cg.shared.global [%0], [%1], 16;"
                 :: "r"(dst), "l"(src) : "memory");
}
__device__ __forceinline__ void cp_commit() {
    asm volatile("cp.async.commit_group;" ::: "memory");
}
template <int N>
__device__ __forceinline__ void cp_wait() {
    asm volatile("cp.async.wait_group %0;" :: "n"(N) : "memory");
}
__device__ __forceinline__ void pair_bar(int id) {
    asm volatile("bar.sync %0, 64;" :: "r"(id) : "memory");
}
__device__ __forceinline__ void ldsm4(uint32_t* r, uint32_t addr) {
    asm volatile("ldmatrix.sync.aligned.m8n8.x4.shared.b16 {%0,%1,%2,%3}, [%4];"
                 : "=r"(r[0]), "=r"(r[1]), "=r"(r[2]), "=r"(r[3]) : "r"(addr));
}
__device__ __forceinline__ void mma16816(float* d, const uint32_t* a, const uint32_t* b) {
    asm volatile(
        "mma.sync.aligned.m16n8k16.row.col.f32.bf16.bf16.f32 "
        "{%0,%1,%2,%3}, {%4,%5,%6,%7}, {%8,%9}, {%0,%1,%2,%3};"
        : "+f"(d[0]), "+f"(d[1]), "+f"(d[2]), "+f"(d[3])
        : "r"(a[0]), "r"(a[1]), "r"(a[2]), "r"(a[3]), "r"(b[0]), "r"(b[1]));
}
__device__ __forceinline__ float ex2f(float x) {
    float y;
    asm("ex2.approx.ftz.f32 %0, %1;" : "=f"(y) : "f"(x));
    return y;
}

// ---------------------------------------------------------------------
// Kernel 1: prep — bf16 hi/lo split (Q scaled by inv_t*log2e) + exact
// fp32 diagonal dot. 256 threads / block, 4 rows per block.
// ---------------------------------------------------------------------
__global__ void __launch_bounds__(256)
prep_kernel(const float* __restrict__ Q, const float* __restrict__ K) {
    const int row = blockIdx.x * 4 + (threadIdx.x >> 6);
    const int lt = threadIdx.x & 63;      // 0..63, 4 elems each

    float4 q4 = ((const float4*)(Q + (size_t)row * DDIM))[lt];
    float4 k4 = ((const float4*)(K + (size_t)row * DDIM))[lt];

    float dot = q4.x * k4.x + q4.y * k4.y + q4.z * k4.z + q4.w * k4.w;

    float qs[4] = {q4.x * QSCALE_F, q4.y * QSCALE_F, q4.z * QSCALE_F, q4.w * QSCALE_F};
    float kv[4] = {k4.x, k4.y, k4.z, k4.w};
    __nv_bfloat16 qh[4], ql[4], kh[4], kl[4];
#pragma unroll
    for (int i = 0; i < 4; i++) {
        qh[i] = __float2bfloat16(qs[i]);
        ql[i] = __float2bfloat16(qs[i] - __bfloat162float(qh[i]));
        kh[i] = __float2bfloat16(kv[i]);
        kl[i] = __float2bfloat16(kv[i] - __bfloat162float(kh[i]));
    }
    size_t b2 = (size_t)row * (DDIM / 2) + lt * 2;
    ((__nv_bfloat162*)g_Qh)[b2]     = __halves2bfloat162(qh[0], qh[1]);
    ((__nv_bfloat162*)g_Qh)[b2 + 1] = __halves2bfloat162(qh[2], qh[3]);
    ((__nv_bfloat162*)g_Ql)[b2]     = __halves2bfloat162(ql[0], ql[1]);
    ((__nv_bfloat162*)g_Ql)[b2 + 1] = __halves2bfloat162(ql[2], ql[3]);
    ((__nv_bfloat162*)g_Kh)[b2]     = __halves2bfloat162(kh[0], kh[1]);
    ((__nv_bfloat162*)g_Kh)[b2 + 1] = __halves2bfloat162(kh[2], kh[3]);
    ((__nv_bfloat162*)g_Kl)[b2]     = __halves2bfloat162(kl[0], kl[1]);
    ((__nv_bfloat162*)g_Kl)[b2 + 1] = __halves2bfloat162(kl[2], kl[3]);

#pragma unroll
    for (int o = 16; o > 0; o >>= 1)
        dot += __shfl_xor_sync(0xffffffffu, dot, o);
    __shared__ float red[8];
    const int wid = threadIdx.x >> 5;
    if ((threadIdx.x & 31) == 0) red[wid] = dot;
    __syncthreads();
    if ((threadIdx.x & 63) == 0)
        g_diag[row] = red[wid] + red[wid + 1];
}

// ---------------------------------------------------------------------
// Kernel 2: persistent mma.sync bf16 GEMM + per-tile softmax partials.
// grid = #SMs. 256 threads = 8 warps, grid 2(M)x4(N), warp tile 64x64.
// Warp pair p owns B columns [64p, 64p+64) (loads + reads + pair bar).
// Pair p staggered by p*800 cyc after each A load so epilogue MUFU
// bursts de-align across the SMSP-sharing pairs.
// SMEM: A = Qh|Ql [128x256] (128KB), B 3-stage ring (3x32KB).
// ---------------------------------------------------------------------
#define NSTAGE    3
#define A_BYTES   (2 * 128 * 512)          // 131072
#define B_STAGE   (256 * 128)              // 32768
#define SMEM_DYN  (512 + A_BYTES + NSTAGE * B_STAGE)

__global__ void __launch_bounds__(256, 1)
gemm_lse_kernel(int ncta) {
    extern __shared__ char dsm[];
    const uint32_t base = (smem_u32(dsm) + 127u) & ~127u;
    const uint32_t A0 = base;                    // Qh [128][256], then Ql
    const uint32_t B0 = base + A_BYTES;          // NSTAGE stages

    const int tid = threadIdx.x;
    const int wid = tid >> 5, lane = tid & 31;
    const int warp_m = wid & 1;                  // 0..1 (rows of 64)
    const int warp_n = wid >> 1;                 // 0..3 (cols of 64)
    const int pair = warp_n;
    const int tp = tid & 63;

    const int ustart = (blockIdx.x * UNITS) / ncta;
    const int uendall = ((blockIdx.x + 1) * UNITS) / ncta;

    // ---- per-thread B load descriptors: pair's 64-col slice, 8 x 16B ----
    uint32_t bsrcoff[8], bdst[8];
#pragma unroll
    for (int ii = 0; ii < 8; ii++) {
        int idx = ii * 64 + tp;                 // 0..511 within slice
        int nB = pair * 64 + (idx >> 3);
        int kc = idx & 7;
        bsrcoff[ii] = (uint32_t)(nB * DDIM + kc * 8);
        bdst[ii] = (uint32_t)(nB * 128 + ((kc ^ (nB & 7)) << 4));
    }

    // ---- compute-side address precompute ----
    int rowA[4], rswA[4];
#pragma unroll
    for (int mi = 0; mi < 4; mi++) {
        rowA[mi] = warp_m * 64 + mi * 16 + (lane & 7) + ((lane & 8) ? 8 : 0);
        rswA[mi] = rowA[mi] & 7;
    }
    const int khalf = (lane >> 4) & 1;
    const int hhB = (lane >> 3) & 1;
    uint32_t bOff[4]; int bsw[4];
#pragma unroll
    for (int gp = 0; gp < 4; gp++) {
        int gg = 2 * gp + ((lane >> 4) & 1);
        int nB = warp_n * 64 + gg * 8 + (lane & 7);
        bOff[gp] = (uint32_t)(nB * 128);
        bsw[gp] = nB & 7;
    }

    float acc[4][8][4];
#pragma unroll
    for (int mi = 0; mi < 4; mi++)
#pragma unroll
        for (int g = 0; g < 8; g++)
#pragma unroll
            for (int v = 0; v < 4; v++) acc[mi][g][v] = 0.f;

    for (int u0 = ustart; u0 < uendall; ) {
        const int rt = u0 >> 5;                  // rowtile
        const int u1 = min(uendall, (rt + 1) << 5);
        const int rowBase = rt << 7;
        const int nch = (u1 - u0) * CHUNKS_PT;

        // ---- load A (Qh,Ql rows rowBase..+127), swizzled ----
        for (int ii = 0; ii < 32; ii++) {
            int idx = ii * 256 + tid;           // 0..8191 16B-chunks
            int half = idx >> 12;
            int rest = idx & 4095;
            int row = rest >> 5, kc = rest & 31;
            const __nv_bfloat16* src =
                (half ? g_Ql : g_Qh) + (size_t)(rowBase + row) * DDIM + kc * 8;
            cp16(A0 + half * 65536 + row * 512 +
                 (((uint32_t)(kc ^ (row & 7))) << 4), src);
        }
        cp_commit();   // group: A

        auto loadB = [&](int gc) {
            int unit = u0 + gc / CHUNKS_PT;
            int sub = gc % CHUNKS_PT;
            int ctile = unit & 31;
            int kc4 = sub >> 1, h = sub & 1;    // h=0: Kh, h=1: Kl
            const __nv_bfloat16* bsrc = h ? g_Kl : g_Kh;
            const __nv_bfloat16* srow =
                bsrc + (size_t)(ctile * 256) * DDIM + kc4 * 64;
            uint32_t dstB = B0 + (uint32_t)(gc % NSTAGE) * B_STAGE;
#pragma unroll
            for (int ii = 0; ii < 8; ii++)
                cp16(dstB + bdst[ii], srow + bsrcoff[ii]);
        };

        loadB(0); cp_commit();
        loadB(1); cp_commit();
        cp_wait<0>();
        __syncthreads();     // A + B0,B1 resident for everyone

        // ---- stagger: seed inter-pair drift so epilogues de-align ----
        if (pair != 0) {
            unsigned long long t0 = clock64();
            unsigned long long dl = (unsigned long long)(pair * 800);
            while (clock64() - t0 < dl) { }
        }

        for (int c = 0; c < nch; c++) {
            cp_wait<1>();            // own slice of B(c) resident
            pair_bar(pair + 1);      // partner done with chunk c-1

            if (c + 2 < nch) loadB(c + 2);
            cp_commit();             // unconditional: keeps wait<1> exact

            const int sub = c % CHUNKS_PT;
            const int kc4 = sub >> 1, h = sub & 1;
            const uint32_t Bst = B0 + (uint32_t)(c % NSTAGE) * B_STAGE;

#pragma unroll
            for (int ks = 0; ks < 4; ks++) {
                const int k0c = (kc4 * 64 + ks * 16) >> 3;   // even
                const uint32_t ach = (uint32_t)(k0c | khalf);
                // preissue all frag loads (A hi, A lo, B) for ILP
                uint32_t a1[4][4], a2[4][4];
#pragma unroll
                for (int mi = 0; mi < 4; mi++)
                    ldsm4(a1[mi], A0 + (uint32_t)rowA[mi] * 512 +
                                  (((ach ^ (uint32_t)rswA[mi])) << 4));
                if (h == 0) {
#pragma unroll
                    for (int mi = 0; mi < 4; mi++)
                        ldsm4(a2[mi], A0 + 65536u + (uint32_t)rowA[mi] * 512 +
                                      (((ach ^ (uint32_t)rswA[mi])) << 4));
                }
                uint32_t b[8][2];
#pragma unroll
                for (int gp = 0; gp < 4; gp++) {
                    uint32_t t4[4];
                    uint32_t ch = (uint32_t)(ks * 2 + hhB);
                    ldsm4(t4, Bst + bOff[gp] + ((ch ^ (uint32_t)bsw[gp]) << 4));
                    b[2 * gp][0] = t4[0]; b[2 * gp][1] = t4[1];
                    b[2 * gp + 1][0] = t4[2]; b[2 * gp + 1][1] = t4[3];
                }
                // pass 1: Qh x B
#pragma unroll
                for (int mi = 0; mi < 4; mi++)
#pragma unroll
                    for (int g = 0; g < 8; g++)
                        mma16816(acc[mi][g], a1[mi], b[g]);
                // pass 2 (Kh chunks only): Ql x B, reusing b frags
                if (h == 0) {
#pragma unroll
                    for (int mi = 0; mi < 4; mi++)
#pragma unroll
                        for (int g = 0; g < 8; g++)
                            mma16816(acc[mi][g], a2[mi], b[g]);
                }
            }

            if (sub == CHUNKS_PT - 1) {
                // ---- per-tile softmax partial: fresh (m, s), write out ----
                const int unit = u0 + c / CHUNKS_PT;
                const int slot = (unit & 31) * 4 + warp_n;
#pragma unroll
                for (int mi = 0; mi < 4; mi++) {
#pragma unroll
                    for (int p = 0; p < 2; p++) {
                        float rm = acc[mi][0][2 * p];
#pragma unroll
                        for (int g = 0; g < 8; g++) {
                            rm = fmaxf(rm, acc[mi][g][2 * p]);
                            rm = fmaxf(rm, acc[mi][g][2 * p + 1]);
                        }
                        rm = fmaxf(rm, __shfl_xor_sync(0xffffffffu, rm, 1));
                        rm = fmaxf(rm, __shfl_xor_sync(0xffffffffu, rm, 2));
                        float ssum = 0.f;
#pragma unroll
                        for (int g = 0; g < 8; g++) {
                            ssum += ex2f(acc[mi][g][2 * p] - rm);
                            ssum += ex2f(acc[mi][g][2 * p + 1] - rm);
                        }
                        ssum += __shfl_xor_sync(0xffffffffu, ssum, 1);
                        ssum += __shfl_xor_sync(0xffffffffu, ssum, 2);
                        if ((lane & 3) == 0) {
                            int row = rowBase + warp_m * 64 + mi * 16 +
                                      (lane >> 2) + 8 * p;
                            g_m[row * NSLOT + slot] = rm;
                            g_s[row * NSLOT + slot] = ssum;
                        }
                    }
                }
#pragma unroll
                for (int mi = 0; mi < 4; mi++)
#pragma unroll
                    for (int g = 0; g < 8; g++)
#pragma unroll
                        for (int v = 0; v < 4; v++) acc[mi][g][v] = 0.f;
            }
        }

        cp_wait<0>();
        __syncthreads();     // all pairs done before A overwrite
        u0 = u1;
    }
}

// ---------------------------------------------------------------------
// Kernel 3: combine 128 partials per row into the loss. 1 warp / row.
// ---------------------------------------------------------------------
__global__ void __launch_bounds__(256)
combine_kernel(float* __restrict__ out) {
    int row = (blockIdx.x * blockDim.x + threadIdx.x) >> 5;
    int lane = threadIdx.x & 31;
    if (row >= N_TOT) return;

    float4 mv = ((const float4*)(g_m + (size_t)row * NSLOT))[lane];
    float4 sv = ((const float4*)(g_s + (size_t)row * NSLOT))[lane];

    float M = fmaxf(fmaxf(mv.x, mv.y), fmaxf(mv.z, mv.w));
#pragma unroll
    for (int o = 16; o > 0; o >>= 1)
        M = fmaxf(M, __shfl_xor_sync(0xffffffffu, M, o));

    float S = sv.x * ex2f(mv.x - M) + sv.y * ex2f(mv.y - M) +
              sv.z * ex2f(mv.z - M) + sv.w * ex2f(mv.w - M);
#pragma unroll
    for (int o = 16; o > 0; o >>= 1)
        S += __shfl_xor_sync(0xffffffffu, S, o);

    if (lane == 0)
        out[row] = LN2_F * (M + log2f(S)) - INV_T_F * g_diag[row];
}

// ---------------------------------------------------------------------
extern "C" void kernel_launch(void* const* d_in, const int* in_sizes, int n_in,
                              void* d_out, int out_size) {
    const float* Q = (const float*)d_in[0];
    const float* K = (const float*)d_in[1];
    float* out = (float*)d_out;

    cudaFuncSetAttribute(gemm_lse_kernel,
                         cudaFuncAttributeMaxDynamicSharedMemorySize, SMEM_DYN);

    int nsm = 148;
    cudaDeviceGetAttribute(&nsm, cudaDevAttrMultiProcessorCount, 0);
    if (nsm < 8) nsm = 148;
    if (nsm > 512) nsm = 512;

    prep_kernel<<<N_TOT / 4, 256>>>(Q, K);
    gemm_lse_kernel<<<nsm, 256, SMEM_DYN>>>(nsm);
    combine_kernel<<<N_TOT * 32 / 256, 256>>>(out);
}